// round 2
// baseline (speedup 1.0000x reference)
#include <cuda_runtime.h>
#include <mma.h>
#include <math.h>

using namespace nvcuda;

// Problem constants
#define NB   8
#define NC   512
#define NL   1024          // H*W
#define NS   77
#define NCTX 768
#define NH   8
#define HD   64
#define NG   32
#define C3   (3*NC)
#define FF   (4*NC)

// GEMM tile config
#define BM 128
#define BN 128
#define BK 16
#define LDA_S 20           // As ld (multiple of 4 floats = 16B)
#define LDB_S 132          // Bs ld
#define LDST 20            // stage ld

// ---------------- scratch (device globals) ----------------------------------
__device__ float g_h1 [NB*NC*NL];
__device__ float g_hn [NB*NC*NL];
__device__ float g_qkv[NB*C3*NL];
__device__ float g_sc [NB*NH*NL*NL];
__device__ float g_sao[NB*NC*NL];
__device__ float g_hc [NB*NC*NL];
__device__ float g_q2 [NB*NC*NL];
__device__ float g_k2 [NB*NC*NS];
__device__ float g_v2 [NB*NC*NS];
__device__ float g_s2 [NB*NH*NL*NS];
__device__ float g_ca [NB*NC*NL];
__device__ float g_f1 [NB*FF*NL];

// ---------------- GroupNorm --------------------------------------------------
__global__ void groupnorm_kernel(const float* __restrict__ x,
                                 const float* __restrict__ gamma,
                                 const float* __restrict__ beta,
                                 float* __restrict__ out)
{
    const int cpg = NC / NG;                 // 16
    const int n   = cpg * NL;                // 16384
    int bg = blockIdx.x;
    int g  = bg % NG;
    long long base = (long long)bg * n;
    const float* xp = x + base;

    float sum = 0.f, sq = 0.f;
    for (int i = threadIdx.x; i < n; i += blockDim.x) {
        float v = xp[i];
        sum += v; sq += v * v;
    }
    __shared__ float s1[256], s2[256];
    s1[threadIdx.x] = sum; s2[threadIdx.x] = sq;
    __syncthreads();
    for (int s = 128; s > 0; s >>= 1) {
        if (threadIdx.x < s) {
            s1[threadIdx.x] += s1[threadIdx.x + s];
            s2[threadIdx.x] += s2[threadIdx.x + s];
        }
        __syncthreads();
    }
    float mean = s1[0] / n;
    float var  = s2[0] / n - mean * mean;
    float rstd = rsqrtf(var + 1e-5f);

    for (int i = threadIdx.x; i < n; i += blockDim.x) {
        int c = g * cpg + i / NL;
        out[base + i] = (xp[i] - mean) * rstd * gamma[c] + beta[c];
    }
}

// ---------------- generic batched TF32 tensor-core GEMM ----------------------
// C[z][M,N] = op(A)[z] * op(B)[z]  (+bias per M-row)(+epilogue)
// TA: A logical [m][k] = Az[k*lda + m]   (else Az[m*lda + k])
// TB: B logical [k][n] = Bz[n*ldb + k]   (else Bz[k*ldb + n])
// z = blockIdx.z; b = z/nh, h = z%nh; ptr += b*Sb + h*Sh per operand.
// epi: 0 none | 1 gelu | 2 +res (and +res2 if set) | 3 *scale
template<bool TA, bool TB>
__global__ void __launch_bounds__(256)
gemm_tf32(const float* __restrict__ A, int lda, long long aSb, long long aSh,
          const float* __restrict__ B, int ldb, long long bSb, long long bSh,
          float*       __restrict__ C, int ldc, long long cSb, long long cSh,
          const float* __restrict__ bias,
          const float* __restrict__ res, const float* __restrict__ res2,
          int M, int N, int K, int nh, int epi, float scale)
{
    __shared__ float As[BM * LDA_S];
    __shared__ float Bs[BK * LDB_S];
    __shared__ float stage[8 * 16 * LDST];

    int z  = blockIdx.z;
    int bb = z / nh, hh = z - bb * nh;
    const float* Az = A + (long long)bb * aSb + (long long)hh * aSh;
    const float* Bz = B + (long long)bb * bSb + (long long)hh * bSh;
    float*       Cz = C + (long long)bb * cSb + (long long)hh * cSh;
    const float* Rz  = res  ? res  + (long long)bb * cSb + (long long)hh * cSh : nullptr;
    const float* R2z = res2 ? res2 + (long long)bb * cSb + (long long)hh * cSh : nullptr;

    int m0 = blockIdx.y * BM, n0 = blockIdx.x * BN;
    int tid = threadIdx.x;
    int wid = tid >> 5, lane = tid & 31;
    int wm = wid >> 1, wn = wid & 1;           // 4x2 warps; warp tile 32x64

    wmma::fragment<wmma::accumulator, 16, 16, 8, float> acc[2][4];
#pragma unroll
    for (int i = 0; i < 2; i++)
#pragma unroll
        for (int j = 0; j < 4; j++) wmma::fill_fragment(acc[i][j], 0.f);

    for (int k0 = 0; k0 < K; k0 += BK) {
        // load A tile -> As[m][k]
#pragma unroll
        for (int p = 0; p < (BM*BK)/256; p++) {
            int idx = tid + p * 256;
            int m, k;
            if (TA) { m = idx & (BM-1); k = idx >> 7; }
            else    { k = idx & (BK-1); m = idx >> 4; }
            int gm = m0 + m, gk = k0 + k;
            float v = 0.f;
            if (gm < M && gk < K)
                v = TA ? Az[(long long)gk * lda + gm]
                       : Az[(long long)gm * lda + gk];
            As[m * LDA_S + k] = v;
        }
        // load B tile -> Bs[k][n]
#pragma unroll
        for (int p = 0; p < (BK*BN)/256; p++) {
            int idx = tid + p * 256;
            int k, n;
            if (TB) { k = idx & (BK-1); n = idx >> 4; }
            else    { n = idx & (BN-1); k = idx >> 7; }
            int gk = k0 + k, gn = n0 + n;
            float v = 0.f;
            if (gk < K && gn < N)
                v = TB ? Bz[(long long)gn * ldb + gk]
                       : Bz[(long long)gk * ldb + gn];
            Bs[k * LDB_S + n] = v;
        }
        __syncthreads();

#pragma unroll
        for (int kk = 0; kk < BK; kk += 8) {
            wmma::fragment<wmma::matrix_a, 16, 16, 8, wmma::precision::tf32, wmma::row_major> af[2];
            wmma::fragment<wmma::matrix_b, 16, 16, 8, wmma::precision::tf32, wmma::row_major> bf[4];
#pragma unroll
            for (int i = 0; i < 2; i++) {
                wmma::load_matrix_sync(af[i], &As[(wm*32 + i*16) * LDA_S + kk], LDA_S);
#pragma unroll
                for (int t = 0; t < af[i].num_elements; t++)
                    af[i].x[t] = wmma::__float_to_tf32(af[i].x[t]);
            }
#pragma unroll
            for (int j = 0; j < 4; j++) {
                wmma::load_matrix_sync(bf[j], &Bs[kk * LDB_S + wn*64 + j*16], LDB_S);
#pragma unroll
                for (int t = 0; t < bf[j].num_elements; t++)
                    bf[j].x[t] = wmma::__float_to_tf32(bf[j].x[t]);
            }
#pragma unroll
            for (int i = 0; i < 2; i++)
#pragma unroll
                for (int j = 0; j < 4; j++)
                    wmma::mma_sync(acc[i][j], af[i], bf[j], acc[i][j]);
        }
        __syncthreads();
    }

    // epilogue: per-fragment stage through smem for guarded scalar writes
    float* st = &stage[wid * 16 * LDST];
#pragma unroll
    for (int i = 0; i < 2; i++) {
#pragma unroll
        for (int j = 0; j < 4; j++) {
            wmma::store_matrix_sync(st, acc[i][j], LDST, wmma::mem_row_major);
            __syncwarp();
#pragma unroll
            for (int e = 0; e < 8; e++) {
                int idx = lane + e * 32;         // 0..255
                int rr = idx >> 4, cc = idx & 15;
                int gr = m0 + wm*32 + i*16 + rr;
                int gc = n0 + wn*64 + j*16 + cc;
                if (gr < M && gc < N) {
                    float v = st[rr * LDST + cc];
                    if (bias) v += bias[gr];
                    if (epi == 1) {
                        v = 0.5f * v * (1.0f + erff(v * 0.70710678118654752f));
                    } else if (epi == 2) {
                        v += Rz[(long long)gr * ldc + gc];
                        if (R2z) v += R2z[(long long)gr * ldc + gc];
                    } else if (epi == 3) {
                        v *= scale;
                    }
                    Cz[(long long)gr * ldc + gc] = v;
                }
            }
            __syncwarp();
        }
    }
}

// ---------------- row softmax (in place) -------------------------------------
__global__ void softmax_kernel(float* __restrict__ S, int N)
{
    long long row = blockIdx.x;
    float* p = S + row * N;
    int tid = threadIdx.x;
    __shared__ float red[128];

    float m = -1e30f;
    for (int j = tid; j < N; j += 128) m = fmaxf(m, p[j]);
    red[tid] = m; __syncthreads();
    for (int s = 64; s > 0; s >>= 1) {
        if (tid < s) red[tid] = fmaxf(red[tid], red[tid + s]);
        __syncthreads();
    }
    m = red[0]; __syncthreads();

    float sum = 0.f;
    for (int j = tid; j < N; j += 128) {
        float e = __expf(p[j] - m);
        p[j] = e; sum += e;
    }
    red[tid] = sum; __syncthreads();
    for (int s = 64; s > 0; s >>= 1) {
        if (tid < s) red[tid] += red[tid + s];
        __syncthreads();
    }
    float inv = 1.0f / red[0];
    for (int j = tid; j < N; j += 128) p[j] *= inv;
}

// ---------------- launch ------------------------------------------------------
extern "C" void kernel_launch(void* const* d_in, const int* in_sizes, int n_in,
                              void* d_out, int out_size)
{
    const float* x        = (const float*)d_in[0];
    const float* context  = (const float*)d_in[1];
    const float* gn_in_g  = (const float*)d_in[2];
    const float* gn_in_b  = (const float*)d_in[3];
    const float* sa_gn_g  = (const float*)d_in[4];
    const float* sa_gn_b  = (const float*)d_in[5];
    const float* qkv_w    = (const float*)d_in[6];
    const float* qkv_b    = (const float*)d_in[7];
    const float* sa_pw    = (const float*)d_in[8];
    const float* sa_pb    = (const float*)d_in[9];
    const float* q_w      = (const float*)d_in[10];
    const float* q_b      = (const float*)d_in[11];
    const float* k_w      = (const float*)d_in[12];
    const float* k_b      = (const float*)d_in[13];
    const float* v_w      = (const float*)d_in[14];
    const float* v_b      = (const float*)d_in[15];
    const float* ca_pw    = (const float*)d_in[16];
    const float* ca_pb    = (const float*)d_in[17];
    const float* w1       = (const float*)d_in[18];
    const float* b1       = (const float*)d_in[19];
    const float* w2       = (const float*)d_in[20];
    const float* b2       = (const float*)d_in[21];
    float* out = (float*)d_out;

    float *h1, *hn, *qkv, *sc, *sao, *hc, *q2v, *k2, *v2, *s2, *ca, *f1;
    cudaGetSymbolAddress((void**)&h1,  g_h1);
    cudaGetSymbolAddress((void**)&hn,  g_hn);
    cudaGetSymbolAddress((void**)&qkv, g_qkv);
    cudaGetSymbolAddress((void**)&sc,  g_sc);
    cudaGetSymbolAddress((void**)&sao, g_sao);
    cudaGetSymbolAddress((void**)&hc,  g_hc);
    cudaGetSymbolAddress((void**)&q2v, g_q2);
    cudaGetSymbolAddress((void**)&k2,  g_k2);
    cudaGetSymbolAddress((void**)&v2,  g_v2);
    cudaGetSymbolAddress((void**)&s2,  g_s2);
    cudaGetSymbolAddress((void**)&ca,  g_ca);
    cudaGetSymbolAddress((void**)&f1,  g_f1);

    const float scale = 0.125f;
    const long long CL  = (long long)NC * NL;
    const long long C3L = (long long)C3 * NL;
    const long long HDL = (long long)HD * NL;
    const long long HDS = (long long)HD * NS;
    const long long LL  = (long long)NL * NL;
    const long long LS  = (long long)NL * NS;
    const long long CS  = (long long)NC * NS;
    const long long FL  = (long long)FF * NL;

    // 1-2) GroupNorms
    groupnorm_kernel<<<NB * NG, 256>>>(x,  gn_in_g, gn_in_b, h1);
    groupnorm_kernel<<<NB * NG, 256>>>(h1, sa_gn_g, sa_gn_b, hn);

    // 3) qkv = qkv_w[1536,512] * hn[b][512,1024] + qkv_b
    gemm_tf32<false,false><<<dim3(NL/BN, C3/BM, NB), 256>>>(
        qkv_w, NC, 0, 0,  hn, NL, CL, 0,  qkv, NL, C3L, 0,
        qkv_b, nullptr, nullptr, C3, NL, NC, 1, 0, 1.f);

    // 4) self scores: S[i,j] = scale * sum_d Q[d,i] K[d,j]
    gemm_tf32<true,false><<<dim3(NL/BN, NL/BM, NB*NH), 256>>>(
        qkv,             NL, C3L, HDL,
        qkv + (long long)NC*NL, NL, C3L, HDL,
        sc, NL, (long long)NH*LL, LL,
        nullptr, nullptr, nullptr, NL, NL, HD, NH, 3, scale);

    // 5) softmax rows of 1024
    softmax_kernel<<<NB*NH*NL, 128>>>(sc, NL);

    // 6) PV: sao[d,i] = sum_j V[d,j] P[i,j]
    gemm_tf32<false,true><<<dim3(NL/BN, 1, NB*NH), 256>>>(
        qkv + 2LL*NC*NL, NL, C3L, HDL,
        sc, NL, (long long)NH*LL, LL,
        sao, NL, CL, HDL,
        nullptr, nullptr, nullptr, HD, NL, NL, NH, 0, 1.f);

    // 7) hc = sa_proj * sao + bias + h1
    gemm_tf32<false,false><<<dim3(NL/BN, NC/BM, NB), 256>>>(
        sa_pw, NC, 0, 0,  sao, NL, CL, 0,  hc, NL, CL, 0,
        sa_pb, h1, nullptr, NC, NL, NC, 1, 2, 1.f);

    // 8) q2 = q_w * hc + q_b
    gemm_tf32<false,false><<<dim3(NL/BN, NC/BM, NB), 256>>>(
        q_w, NC, 0, 0,  hc, NL, CL, 0,  q2v, NL, CL, 0,
        q_b, nullptr, nullptr, NC, NL, NC, 1, 0, 1.f);

    // 9-10) k2/v2 = W[512,768] * ctx^T[b][768,77] + b
    gemm_tf32<false,true><<<dim3(1, NC/BM, NB), 256>>>(
        k_w, NCTX, 0, 0,  context, NCTX, (long long)NS*NCTX, 0,
        k2, NS, CS, 0, k_b, nullptr, nullptr, NC, NS, NCTX, 1, 0, 1.f);
    gemm_tf32<false,true><<<dim3(1, NC/BM, NB), 256>>>(
        v_w, NCTX, 0, 0,  context, NCTX, (long long)NS*NCTX, 0,
        v2, NS, CS, 0, v_b, nullptr, nullptr, NC, NS, NCTX, 1, 0, 1.f);

    // 11) cross scores [1024 x 77]
    gemm_tf32<true,false><<<dim3(1, NL/BM, NB*NH), 256>>>(
        q2v, NL, CL, HDL,
        k2,  NS, CS, HDS,
        s2,  NS, (long long)NH*LS, LS,
        nullptr, nullptr, nullptr, NL, NS, HD, NH, 3, scale);

    // 12) softmax rows of 77
    softmax_kernel<<<NB*NH*NL, 128>>>(s2, NS);

    // 13) cross PV: ca[d,i] = sum_s V2[d,s] P2[i,s]
    gemm_tf32<false,true><<<dim3(NL/BN, 1, NB*NH), 256>>>(
        v2, NS, CS, HDS,
        s2, NS, (long long)NH*LS, LS,
        ca, NL, CL, HDL,
        nullptr, nullptr, nullptr, HD, NL, NS, NH, 0, 1.f);

    // 14) hc = ca_proj * ca + bias + hc
    gemm_tf32<false,false><<<dim3(NL/BN, NC/BM, NB), 256>>>(
        ca_pw, NC, 0, 0,  ca, NL, CL, 0,  hc, NL, CL, 0,
        ca_pb, hc, nullptr, NC, NL, NC, 1, 2, 1.f);

    // 15) f1 = gelu(w1 * hc + b1)
    gemm_tf32<false,false><<<dim3(NL/BN, FF/BM, NB), 256>>>(
        w1, NC, 0, 0,  hc, NL, CL, 0,  f1, NL, FL, 0,
        b1, nullptr, nullptr, FF, NL, NC, 1, 1, 1.f);

    // 16) out = w2 * f1 + b2 + hc + x   (final residual fused)
    gemm_tf32<false,false><<<dim3(NL/BN, NC/BM, NB), 256>>>(
        w2, FF, 0, 0,  f1, NL, FL, 0,  out, NL, CL, 0,
        b2, hc, x, NC, NL, FF, 1, 2, 1.f);
}

// round 4
// speedup vs baseline: 1.8337x; 1.8337x over previous
#include <cuda_runtime.h>
#include <cstdint>
#include <mma.h>
#include <math.h>
#include <type_traits>

using namespace nvcuda;

// Problem constants
#define NB   8
#define NC   512
#define NL   1024
#define NS   77
#define NSP  128          // padded NS
#define NCTX 768
#define NH   8
#define HD   64
#define NG   32
#define C3   (3*NC)
#define FF   (4*NC)

// ---------------- scratch ----------------------------------------------------
__device__ float g_h1 [NB*NC*NL];
__device__ float g_hn [NB*NC*NL];
__device__ float g_qkv[NB*C3*NL];
__device__ float g_sc [(long long)NB*NH*NL*NL];
__device__ float g_sao[NB*NC*NL];
__device__ float g_hc [NB*NC*NL];
__device__ float g_q2 [NB*NC*NL];
__device__ float g_k2 [NB*NC*NSP];
__device__ float g_v2 [NB*NC*NSP];
__device__ float g_s2 [NB*NH*NL*NSP];
__device__ float g_ca [NB*NC*NL];
__device__ float g_f1 [NB*FF*NL];

// ---------------- helpers -----------------------------------------------------
__device__ __forceinline__ void cp16(void* sdst, const void* gsrc, bool pred) {
    unsigned sa = (unsigned)__cvta_generic_to_shared(sdst);
    int bytes = pred ? 16 : 0;
    asm volatile("cp.async.cg.shared.global [%0], [%1], 16, %2;\n"
                 :: "r"(sa), "l"(gsrc), "r"(bytes));
}
__device__ __forceinline__ void cp_commit() {
    asm volatile("cp.async.commit_group;\n");
}
__device__ __forceinline__ void cp_wait1() {
    asm volatile("cp.async.wait_group 1;\n");
}

// ---------------- GroupNorm ----------------------------------------------------
__global__ void groupnorm_kernel(const float* __restrict__ x,
                                 const float* __restrict__ gamma,
                                 const float* __restrict__ beta,
                                 float* __restrict__ out)
{
    const int cpg = NC / NG;                 // 16
    const int n   = cpg * NL;                // 16384
    int bg = blockIdx.x;
    int g  = bg % NG;
    long long base = (long long)bg * n;
    const float* xp = x + base;

    float sum = 0.f, sq = 0.f;
    for (int i = threadIdx.x; i < n; i += blockDim.x) {
        float v = xp[i];
        sum += v; sq += v * v;
    }
    __shared__ float s1[256], s2[256];
    s1[threadIdx.x] = sum; s2[threadIdx.x] = sq;
    __syncthreads();
    for (int s = 128; s > 0; s >>= 1) {
        if (threadIdx.x < s) {
            s1[threadIdx.x] += s1[threadIdx.x + s];
            s2[threadIdx.x] += s2[threadIdx.x + s];
        }
        __syncthreads();
    }
    float mean = s1[0] / n;
    float var  = s2[0] / n - mean * mean;
    float rstd = rsqrtf(var + 1e-5f);

    for (int i = threadIdx.x; i < n; i += blockDim.x) {
        int c = g * cpg + i / NL;
        out[base + i] = (xp[i] - mean) * rstd * gamma[c] + beta[c];
    }
}

// ---------------- pipelined TF32 tensor-core GEMM ------------------------------
// C[z][M,N] = op(A)[z]*op(B)[z] (+bias)(+epi)
// TA: A[m][k] = Az[k*lda+m]; TB: B[k][n] = Bz[n*ldb+k]
// epi: 0 none | 1 gelu | 2 +res(+res2) | 3 *scale
template<int BM, int WGM, int WGN, bool TA, bool TB>
__global__ void __launch_bounds__(256, 2)
gemm_tc(const float* __restrict__ A, int lda, long long aSb, long long aSh,
        const float* __restrict__ B, int ldb, long long bSb, long long bSh,
        float*       __restrict__ C, int ldc, long long cSb, long long cSh,
        const float* __restrict__ bias,
        const float* __restrict__ res, const float* __restrict__ res2,
        int M, int N, int K, int nh, int epi, float scale, int Nguard)
{
    constexpr int BN = 128, BK = 16;
    constexpr int TM = BM / WGM, TN = BN / WGN;
    constexpr int FM = TM / 16, FN = TN / 16;
    constexpr int ALD = TA ? BM + 4 : BK + 4;
    constexpr int ASZ = TA ? BK * ALD : BM * ALD;
    constexpr int BLD = TB ? BK + 4 : BN + 4;
    constexpr int BSZ = TB ? BN * BLD : BK * BLD;
    constexpr int AF4 = BM * BK / 4;

    __shared__ float As[2][ASZ];
    __shared__ float Bs[2][BSZ];

    int z  = blockIdx.z;
    int bb = z / nh, hh = z - bb * nh;
    const float* Az = A + (long long)bb * aSb + (long long)hh * aSh;
    const float* Bz = B + (long long)bb * bSb + (long long)hh * bSh;
    float*       Cz = C + (long long)bb * cSb + (long long)hh * cSh;
    const float* Rz  = res  ? res  + (long long)bb * cSb + (long long)hh * cSh : nullptr;
    const float* R2z = res2 ? res2 + (long long)bb * cSb + (long long)hh * cSh : nullptr;

    int m0 = blockIdx.y * BM, n0 = blockIdx.x * BN;
    int tid = threadIdx.x;
    int wid = tid >> 5;
    int wm = wid / WGN, wn = wid % WGN;

    using ALayout = typename std::conditional<TA, wmma::col_major, wmma::row_major>::type;
    using BLayout = typename std::conditional<TB, wmma::col_major, wmma::row_major>::type;
    using FragA = wmma::fragment<wmma::matrix_a, 16, 16, 8, wmma::precision::tf32, ALayout>;
    using FragB = wmma::fragment<wmma::matrix_b, 16, 16, 8, wmma::precision::tf32, BLayout>;
    using FragC = wmma::fragment<wmma::accumulator, 16, 16, 8, float>;

    FragC acc[FM][FN];
#pragma unroll
    for (int i = 0; i < FM; i++)
#pragma unroll
        for (int j = 0; j < FN; j++) wmma::fill_fragment(acc[i][j], 0.f);

    auto load_stage = [&](int s, int k0) {
#pragma unroll
        for (int p = 0; p < AF4 / 256; p++) {
            int idx = tid + p * 256;
            if (TA) {
                int k  = idx / (BM / 4);
                int m4 = (idx % (BM / 4)) * 4;
                cp16(&As[s][k * ALD + m4],
                     Az + (long long)(k0 + k) * lda + m0 + m4, true);
            } else {
                int m  = idx >> 2;
                int k4 = (idx & 3) * 4;
                cp16(&As[s][m * ALD + k4],
                     Az + (long long)(m0 + m) * lda + k0 + k4, true);
            }
        }
#pragma unroll
        for (int p = 0; p < 2; p++) {
            int idx = tid + p * 256;
            if (TB) {
                int n  = idx >> 2;
                int k4 = (idx & 3) * 4;
                bool ok = (n0 + n) < Nguard;
                cp16(&Bs[s][n * BLD + k4],
                     Bz + (long long)(n0 + n) * ldb + k0 + k4, ok);
            } else {
                int k  = idx >> 5;
                int n4 = (idx & 31) * 4;
                bool ok = (n0 + n4) < Nguard;
                cp16(&Bs[s][k * BLD + n4],
                     Bz + (long long)(k0 + k) * ldb + n0 + n4, ok);
            }
        }
    };

    auto compute = [&](int s) {
#pragma unroll
        for (int kk = 0; kk < BK; kk += 8) {
            FragA af[FM];
            FragB bf[FN];
#pragma unroll
            for (int i = 0; i < FM; i++) {
                const float* p = TA
                    ? &As[s][kk * ALD + wm * TM + i * 16]
                    : &As[s][(wm * TM + i * 16) * ALD + kk];
                wmma::load_matrix_sync(af[i], p, ALD);
#pragma unroll
                for (int t = 0; t < af[i].num_elements; t++)
                    af[i].x[t] = wmma::__float_to_tf32(af[i].x[t]);
            }
#pragma unroll
            for (int j = 0; j < FN; j++) {
                const float* p = TB
                    ? &Bs[s][(wn * TN + j * 16) * BLD + kk]
                    : &Bs[s][kk * BLD + wn * TN + j * 16];
                wmma::load_matrix_sync(bf[j], p, BLD);
#pragma unroll
                for (int t = 0; t < bf[j].num_elements; t++)
                    bf[j].x[t] = wmma::__float_to_tf32(bf[j].x[t]);
            }
#pragma unroll
            for (int i = 0; i < FM; i++)
#pragma unroll
                for (int j = 0; j < FN; j++)
                    wmma::mma_sync(acc[i][j], af[i], bf[j], acc[i][j]);
        }
    };

    int T = K / BK;
    load_stage(0, 0);
    cp_commit();
    for (int t = 0; t < T; t++) {
        if (t + 1 < T) load_stage((t + 1) & 1, (t + 1) * BK);
        cp_commit();
        cp_wait1();
        __syncthreads();
        compute(t & 1);
        __syncthreads();
    }

    // bias via rank-1 synthetic K-slice
    if (bias) {
        for (int idx = tid; idx < BM * 8; idx += 256) {
            int m = idx % BM, k = idx / BM;
            float v = (k == 0) ? bias[m0 + m] : 0.f;
            if (TA) As[0][k * ALD + m] = v;
            else    As[0][m * ALD + k] = v;
        }
        for (int idx = tid; idx < BN * 8; idx += 256) {
            int n = idx % BN, k = idx / BN;
            float v = (k == 0 && (n0 + n) < Nguard) ? 1.f : 0.f;
            if (TB) Bs[0][n * BLD + k] = v;
            else    Bs[0][k * BLD + n] = v;
        }
        __syncthreads();
        {
            FragA af[FM];
            FragB bf[FN];
#pragma unroll
            for (int i = 0; i < FM; i++) {
                const float* p = TA ? &As[0][wm * TM + i * 16]
                                    : &As[0][(wm * TM + i * 16) * ALD];
                wmma::load_matrix_sync(af[i], p, ALD);
#pragma unroll
                for (int t = 0; t < af[i].num_elements; t++)
                    af[i].x[t] = wmma::__float_to_tf32(af[i].x[t]);
            }
#pragma unroll
            for (int j = 0; j < FN; j++) {
                const float* p = TB ? &Bs[0][(wn * TN + j * 16) * BLD]
                                    : &Bs[0][wn * TN + j * 16];
                wmma::load_matrix_sync(bf[j], p, BLD);
#pragma unroll
                for (int t = 0; t < bf[j].num_elements; t++)
                    bf[j].x[t] = wmma::__float_to_tf32(bf[j].x[t]);
            }
#pragma unroll
            for (int i = 0; i < FM; i++)
#pragma unroll
                for (int j = 0; j < FN; j++)
                    wmma::mma_sync(acc[i][j], af[i], bf[j], acc[i][j]);
        }
    }

    // fragment-native epilogue
#pragma unroll
    for (int i = 0; i < FM; i++) {
#pragma unroll
        for (int j = 0; j < FN; j++) {
            int gr = m0 + wm * TM + i * 16;
            int gc = n0 + wn * TN + j * 16;
            if (epi == 1) {
#pragma unroll
                for (int t = 0; t < acc[i][j].num_elements; t++) {
                    float v = acc[i][j].x[t];
                    acc[i][j].x[t] = 0.5f * v * (1.0f + erff(v * 0.70710678118654752f));
                }
            } else if (epi == 3) {
#pragma unroll
                for (int t = 0; t < acc[i][j].num_elements; t++)
                    acc[i][j].x[t] *= scale;
            }
            if (res) {
                FragC r;
                wmma::load_matrix_sync(r, Rz + (long long)gr * ldc + gc, ldc, wmma::mem_row_major);
#pragma unroll
                for (int t = 0; t < acc[i][j].num_elements; t++)
                    acc[i][j].x[t] += r.x[t];
                if (res2) {
                    wmma::load_matrix_sync(r, R2z + (long long)gr * ldc + gc, ldc, wmma::mem_row_major);
#pragma unroll
                    for (int t = 0; t < acc[i][j].num_elements; t++)
                        acc[i][j].x[t] += r.x[t];
                }
            }
            wmma::store_matrix_sync(Cz + (long long)gr * ldc + gc, acc[i][j], ldc, wmma::mem_row_major);
        }
    }
}

// ---------------- single-pass softmax (row in registers) -----------------------
__global__ void softmax2(float* __restrict__ S, int N, int ld)
{
    long long row = blockIdx.x;
    float* p = S + row * (long long)ld;
    int tid = threadIdx.x;
    int base = tid * 4;
    bool full = (base + 3 < N);

    float v[4];
    if (full) {
        float4 t = *(const float4*)(p + base);
        v[0] = t.x; v[1] = t.y; v[2] = t.z; v[3] = t.w;
    } else {
#pragma unroll
        for (int e = 0; e < 4; e++)
            v[e] = (base + e < N) ? p[base + e] : -1e30f;
    }

    float m = fmaxf(fmaxf(v[0], v[1]), fmaxf(v[2], v[3]));
#pragma unroll
    for (int off = 16; off > 0; off >>= 1)
        m = fmaxf(m, __shfl_xor_sync(0xffffffff, m, off));
    __shared__ float red[8];
    if ((tid & 31) == 0) red[tid >> 5] = m;
    __syncthreads();
    m = red[0];
#pragma unroll
    for (int w = 1; w < 8; w++) m = fmaxf(m, red[w]);
    __syncthreads();

    float sum = 0.f;
#pragma unroll
    for (int e = 0; e < 4; e++) {
        v[e] = (base + e < N) ? __expf(v[e] - m) : 0.f;
        sum += v[e];
    }
#pragma unroll
    for (int off = 16; off > 0; off >>= 1)
        sum += __shfl_xor_sync(0xffffffff, sum, off);
    if ((tid & 31) == 0) red[tid >> 5] = sum;
    __syncthreads();
    sum = 0.f;
#pragma unroll
    for (int w = 0; w < 8; w++) sum += red[w];
    float inv = 1.0f / sum;

    if (full) {
        float4 t; t.x = v[0]*inv; t.y = v[1]*inv; t.z = v[2]*inv; t.w = v[3]*inv;
        *(float4*)(p + base) = t;
    } else {
#pragma unroll
        for (int e = 0; e < 4; e++)
            if (base + e < N) p[base + e] = v[e] * inv;
    }
}

// ---------------- launch --------------------------------------------------------
extern "C" void kernel_launch(void* const* d_in, const int* in_sizes, int n_in,
                              void* d_out, int out_size)
{
    const float* x        = (const float*)d_in[0];
    const float* context  = (const float*)d_in[1];
    const float* gn_in_g  = (const float*)d_in[2];
    const float* gn_in_b  = (const float*)d_in[3];
    const float* sa_gn_g  = (const float*)d_in[4];
    const float* sa_gn_b  = (const float*)d_in[5];
    const float* qkv_w    = (const float*)d_in[6];
    const float* qkv_b    = (const float*)d_in[7];
    const float* sa_pw    = (const float*)d_in[8];
    const float* sa_pb    = (const float*)d_in[9];
    const float* q_w      = (const float*)d_in[10];
    const float* q_b      = (const float*)d_in[11];
    const float* k_w      = (const float*)d_in[12];
    const float* k_b      = (const float*)d_in[13];
    const float* v_w      = (const float*)d_in[14];
    const float* v_b      = (const float*)d_in[15];
    const float* ca_pw    = (const float*)d_in[16];
    const float* ca_pb    = (const float*)d_in[17];
    const float* w1       = (const float*)d_in[18];
    const float* b1       = (const float*)d_in[19];
    const float* w2       = (const float*)d_in[20];
    const float* b2       = (const float*)d_in[21];
    float* out = (float*)d_out;

    float *h1, *hn, *qkv, *sc, *sao, *hc, *q2v, *k2, *v2, *s2, *ca, *f1;
    cudaGetSymbolAddress((void**)&h1,  g_h1);
    cudaGetSymbolAddress((void**)&hn,  g_hn);
    cudaGetSymbolAddress((void**)&qkv, g_qkv);
    cudaGetSymbolAddress((void**)&sc,  g_sc);
    cudaGetSymbolAddress((void**)&sao, g_sao);
    cudaGetSymbolAddress((void**)&hc,  g_hc);
    cudaGetSymbolAddress((void**)&q2v, g_q2);
    cudaGetSymbolAddress((void**)&k2,  g_k2);
    cudaGetSymbolAddress((void**)&v2,  g_v2);
    cudaGetSymbolAddress((void**)&s2,  g_s2);
    cudaGetSymbolAddress((void**)&ca,  g_ca);
    cudaGetSymbolAddress((void**)&f1,  g_f1);

    const float scale = 0.125f;
    const int BIG = 1 << 30;
    const long long CL  = (long long)NC * NL;
    const long long C3L = (long long)C3 * NL;
    const long long HDL = (long long)HD * NL;
    const long long LL  = (long long)NL * NL;
    const long long FL  = (long long)FF * NL;

    // 1-2) GroupNorms
    groupnorm_kernel<<<NB * NG, 256>>>(x,  gn_in_g, gn_in_b, h1);
    groupnorm_kernel<<<NB * NG, 256>>>(h1, sa_gn_g, sa_gn_b, hn);

    // 3) qkv
    gemm_tc<128,4,2,false,false><<<dim3(NL/128, C3/128, NB), 256>>>(
        qkv_w, NC, 0, 0,  hn, NL, CL, 0,  qkv, NL, C3L, 0,
        qkv_b, nullptr, nullptr, C3, NL, NC, 1, 0, 1.f, BIG);

    // 4) self scores
    gemm_tc<128,4,2,true,false><<<dim3(NL/128, NL/128, NB*NH), 256>>>(
        qkv, NL, C3L, HDL,
        qkv + (long long)NC*NL, NL, C3L, HDL,
        sc, NL, (long long)NH*LL, LL,
        nullptr, nullptr, nullptr, NL, NL, HD, NH, 3, scale, BIG);

    // 5) softmax 1024
    softmax2<<<NB*NH*NL, 256>>>(sc, NL, NL);

    // 6) self PV
    gemm_tc<64,2,4,false,true><<<dim3(NL/128, 1, NB*NH), 256>>>(
        qkv + 2LL*NC*NL, NL, C3L, HDL,
        sc, NL, (long long)NH*LL, LL,
        sao, NL, CL, HDL,
        nullptr, nullptr, nullptr, HD, NL, NL, NH, 0, 1.f, BIG);

    // 7) hc = sa_proj*sao + b + h1
    gemm_tc<128,4,2,false,false><<<dim3(NL/128, NC/128, NB), 256>>>(
        sa_pw, NC, 0, 0,  sao, NL, CL, 0,  hc, NL, CL, 0,
        sa_pb, h1, nullptr, NC, NL, NC, 1, 2, 1.f, BIG);

    // 8) q2
    gemm_tc<128,4,2,false,false><<<dim3(NL/128, NC/128, NB), 256>>>(
        q_w, NC, 0, 0,  hc, NL, CL, 0,  q2v, NL, CL, 0,
        q_b, nullptr, nullptr, NC, NL, NC, 1, 0, 1.f, BIG);

    // 9-10) k2 / v2  (N padded to 128, guard 77; pads -> 0)
    gemm_tc<128,4,2,false,true><<<dim3(1, NC/128, NB), 256>>>(
        k_w, NCTX, 0, 0,  context, NCTX, (long long)NS*NCTX, 0,
        k2, NSP, (long long)NC*NSP, 0,
        k_b, nullptr, nullptr, NC, NSP, NCTX, 1, 0, 1.f, NS);
    gemm_tc<128,4,2,false,true><<<dim3(1, NC/128, NB), 256>>>(
        v_w, NCTX, 0, 0,  context, NCTX, (long long)NS*NCTX, 0,
        v2, NSP, (long long)NC*NSP, 0,
        v_b, nullptr, nullptr, NC, NSP, NCTX, 1, 0, 1.f, NS);

    // 11) cross scores [1024 x 128pad]
    gemm_tc<128,4,2,true,false><<<dim3(1, NL/128, NB*NH), 256>>>(
        q2v, NL, CL, HDL,
        k2,  NSP, (long long)NC*NSP, (long long)HD*NSP,
        s2,  NSP, (long long)NH*NL*NSP, (long long)NL*NSP,
        nullptr, nullptr, nullptr, NL, NSP, HD, NH, 3, scale, BIG);

    // 12) softmax 77 (pads untouched, remain 0)
    softmax2<<<NB*NH*NL, 256>>>(s2, NS, NSP);

    // 13) cross PV (K=80: pad cols of P are zero)
    gemm_tc<64,2,4,false,true><<<dim3(NL/128, 1, NB*NH), 256>>>(
        v2, NSP, (long long)NC*NSP, (long long)HD*NSP,
        s2, NSP, (long long)NH*NL*NSP, (long long)NL*NSP,
        ca, NL, CL, HDL,
        nullptr, nullptr, nullptr, HD, NL, 80, NH, 0, 1.f, BIG);

    // 14) hc = ca_proj*ca + b + hc
    gemm_tc<128,4,2,false,false><<<dim3(NL/128, NC/128, NB), 256>>>(
        ca_pw, NC, 0, 0,  ca, NL, CL, 0,  hc, NL, CL, 0,
        ca_pb, hc, nullptr, NC, NL, NC, 1, 2, 1.f, BIG);

    // 15) f1 = gelu(w1*hc + b1)
    gemm_tc<128,4,2,false,false><<<dim3(NL/128, FF/128, NB), 256>>>(
        w1, NC, 0, 0,  hc, NL, CL, 0,  f1, NL, FL, 0,
        b1, nullptr, nullptr, FF, NL, NC, 1, 1, 1.f, BIG);

    // 16) out = w2*f1 + b2 + hc + x
    gemm_tc<128,4,2,false,false><<<dim3(NL/128, NC/128, NB), 256>>>(
        w2, FF, 0, 0,  f1, NL, FL, 0,  out, NL, CL, 0,
        b2, hc, x, NC, NL, FF, 1, 2, 1.f, BIG);
}